// round 1
// baseline (speedup 1.0000x reference)
#include <cuda_runtime.h>

// Problem constants
#define BT      16384      // 16*1024 rows
#define DDIM    512
#define NE      8192
#define BETA    0.25

// Tiling for main argmin-GEMM kernel
#define TM      64         // rows per block
#define TN      256        // codes per tile
#define KC      32         // k-chunk
#define NTHREADS 256

// Output layout (concatenated flattened returns, float32):
// [0, 8388608)            z_q_st
// [8388608]               loss
// [8388609, 8388609+BT)   idx (as float)
// [8404993]               var(idx)
#define ZQ_ELEMS   (BT * DDIM)          // 8388608
#define LOSS_OFF   ZQ_ELEMS
#define IDX_OFF    (ZQ_ELEMS + 1)
#define VAR_OFF    (ZQ_ELEMS + 1 + BT)  // 8404993

// Scratch (no allocations allowed -> __device__ globals)
__device__ float  g_zf2[BT];
__device__ float  g_en2[NE];
__device__ int    g_idx[BT];
__device__ double g_partial[512];

// ---------------------------------------------------------------------------
// en2[n] = sum_k emb[n,k]^2   (square rounded, then added: mimic elementwise
// square followed by reduce; intrinsics prevent fma-contraction)
// ---------------------------------------------------------------------------
__global__ void en2_kernel(const float* __restrict__ emb) {
    int n = blockIdx.x * blockDim.x + threadIdx.x;
    if (n >= NE) return;
    const float* p = emb + (size_t)n * DDIM;
    float s = 0.0f;
    for (int k = 0; k < DDIM; k++) {
        float q = __fmul_rn(p[k], p[k]);
        s = __fadd_rn(s, q);
    }
    g_en2[n] = s;
}

// zf2[r] = sum_k z[r,k]^2
__global__ void zf2_kernel(const float* __restrict__ z) {
    int r = blockIdx.x * blockDim.x + threadIdx.x;
    if (r >= BT) return;
    const float* p = z + (size_t)r * DDIM;
    float s = 0.0f;
    for (int k = 0; k < DDIM; k++) {
        float q = __fmul_rn(p[k], p[k]);
        s = __fadd_rn(s, q);
    }
    g_zf2[r] = s;
}

// ---------------------------------------------------------------------------
// Main kernel: for 64 rows, loop over all 8192 codes in tiles of 256,
// compute dot products via smem-tiled fp32 GEMM (8x8 register micro-tile),
// form d = (zf2 + en2) - 2*dot exactly like the reference, keep running
// argmin with first-index tie-break.
// ---------------------------------------------------------------------------
__global__ __launch_bounds__(NTHREADS, 2)
void argmin_kernel(const float* __restrict__ z, const float* __restrict__ emb) {
    __shared__ float zs[TM][KC + 1];    // [row][k], padded: stores conflict-free
    __shared__ float es[KC][TN + 5];    // [k][code], pad 5: stores conflict-free

    const int tid = threadIdx.x;
    const int tn  = tid & 31;           // 0..31, lane within warp
    const int tm  = tid >> 5;           // 0..7,  warp id
    const int rowBlock = blockIdx.x * TM;
    const int rBase = tm * 8;           // this thread's 8 rows (warp-uniform)

    float zf2r[8];
#pragma unroll
    for (int i = 0; i < 8; i++) zf2r[i] = g_zf2[rowBlock + rBase + i];

    float best_d[8];
    int   best_i[8];
#pragma unroll
    for (int i = 0; i < 8; i++) { best_d[i] = 3.4e38f; best_i[i] = 0; }

    for (int tile = 0; tile < NE / TN; ++tile) {
        const int nBase = tile * TN;
        float acc[8][8];
#pragma unroll
        for (int i = 0; i < 8; i++)
#pragma unroll
            for (int j = 0; j < 8; j++) acc[i][j] = 0.0f;

        for (int kc = 0; kc < DDIM; kc += KC) {
            // load z chunk: 64 rows x 32 k = 512 float4
#pragma unroll
            for (int it = 0; it < 2; ++it) {
                int idx = tid + it * NTHREADS;
                int r  = idx >> 3;
                int k4 = (idx & 7) * 4;
                float4 v = *reinterpret_cast<const float4*>(
                    &z[(size_t)(rowBlock + r) * DDIM + kc + k4]);
                zs[r][k4 + 0] = v.x; zs[r][k4 + 1] = v.y;
                zs[r][k4 + 2] = v.z; zs[r][k4 + 3] = v.w;
            }
            // load emb chunk: 256 codes x 32 k = 2048 float4
#pragma unroll
            for (int it = 0; it < 8; ++it) {
                int idx = tid + it * NTHREADS;
                int c  = idx >> 3;
                int k4 = (idx & 7) * 4;
                float4 v = *reinterpret_cast<const float4*>(
                    &emb[(size_t)(nBase + c) * DDIM + kc + k4]);
                es[k4 + 0][c] = v.x; es[k4 + 1][c] = v.y;
                es[k4 + 2][c] = v.z; es[k4 + 3][c] = v.w;
            }
            __syncthreads();

#pragma unroll 8
            for (int k = 0; k < KC; k++) {
                float a[8], b[8];
#pragma unroll
                for (int i = 0; i < 8; i++) a[i] = zs[rBase + i][k];   // broadcast
#pragma unroll
                for (int j = 0; j < 8; j++) b[j] = es[k][tn + 32 * j]; // lane-linear
#pragma unroll
                for (int i = 0; i < 8; i++)
#pragma unroll
                    for (int j = 0; j < 8; j++)
                        acc[i][j] = fmaf(a[i], b[j], acc[i][j]);
            }
            __syncthreads();
        }

        // epilogue for this code tile: d = (zf2 + en2) - 2*dot, running argmin
#pragma unroll
        for (int j = 0; j < 8; j++) {
            const int n = nBase + tn + 32 * j;  // ascending in j for fixed lane
            const float e2 = __ldg(&g_en2[n]);
#pragma unroll
            for (int i = 0; i < 8; i++) {
                float t = __fadd_rn(zf2r[i], e2);
                float d = __fadd_rn(t, -2.0f * acc[i][j]);  // *2 exact
                if (d < best_d[i]) { best_d[i] = d; best_i[i] = n; }
            }
        }
    }

    // reduce across the 32 lanes of each warp (all hold the same 8 rows);
    // lexicographic (d, idx) to preserve first-index tie-break
#pragma unroll
    for (int i = 0; i < 8; i++) {
        float bd = best_d[i];
        int   bi = best_i[i];
        for (int off = 16; off > 0; off >>= 1) {
            float od = __shfl_down_sync(0xffffffffu, bd, off);
            int   oi = __shfl_down_sync(0xffffffffu, bi, off);
            if (od < bd || (od == bd && oi < bi)) { bd = od; bi = oi; }
        }
        if (tn == 0) g_idx[rowBlock + rBase + i] = bi;
    }
}

// ---------------------------------------------------------------------------
// Gather z_q = emb[idx], write to out, accumulate (z_q - z)^2 in double.
// Deterministic block-tree reduction into g_partial[512].
// ---------------------------------------------------------------------------
__global__ void gather_loss_kernel(const float* __restrict__ z,
                                   const float* __restrict__ emb,
                                   float* __restrict__ out) {
    __shared__ double red[256];
    const int bid = blockIdx.x;           // 512 blocks
    const int base = bid * (ZQ_ELEMS / 512);  // 16384 elems per block
    double s = 0.0;
#pragma unroll 4
    for (int it = 0; it < 64; ++it) {
        int e = base + threadIdx.x + it * 256;
        int row = e >> 9;
        int k   = e & 511;
        float v = emb[(size_t)g_idx[row] * DDIM + k];
        out[e] = v;
        float diff = v - z[e];
        s += (double)diff * (double)diff;
    }
    red[threadIdx.x] = s;
    __syncthreads();
    for (int off = 128; off > 0; off >>= 1) {
        if (threadIdx.x < off) red[threadIdx.x] += red[threadIdx.x + off];
        __syncthreads();
    }
    if (threadIdx.x == 0) g_partial[bid] = red[0];
}

// ---------------------------------------------------------------------------
// Final scalars: loss, idx->float, var(idx). Single block, deterministic.
// ---------------------------------------------------------------------------
__global__ void finalize_kernel(float* __restrict__ out) {
    __shared__ double rs[256], rs2[256];
    double s = 0.0, s2 = 0.0;
    for (int i = threadIdx.x; i < BT; i += 256) {
        int iv = g_idx[i];
        out[IDX_OFF + i] = (float)iv;
        double dv = (double)iv;
        s  += dv;
        s2 += dv * dv;
    }
    rs[threadIdx.x] = s;
    rs2[threadIdx.x] = s2;
    __syncthreads();
    for (int off = 128; off > 0; off >>= 1) {
        if (threadIdx.x < off) {
            rs[threadIdx.x]  += rs[threadIdx.x + off];
            rs2[threadIdx.x] += rs2[threadIdx.x + off];
        }
        __syncthreads();
    }
    if (threadIdx.x == 0) {
        double ls = 0.0;
        for (int i = 0; i < 512; i++) ls += g_partial[i];
        double mse = ls / (double)ZQ_ELEMS;
        out[LOSS_OFF] = (float)((1.0 + BETA) * mse);
        double mean = rs[0] / (double)BT;
        double var  = rs2[0] / (double)BT - mean * mean;
        out[VAR_OFF] = (float)var;
    }
}

// ---------------------------------------------------------------------------
extern "C" void kernel_launch(void* const* d_in, const int* in_sizes, int n_in,
                              void* d_out, int out_size) {
    const float* z   = (const float*)d_in[0];   // [16,1024,512]
    const float* emb = (const float*)d_in[1];   // [8192,512]
    float* out = (float*)d_out;

    en2_kernel<<<NE / 256, 256>>>(emb);
    zf2_kernel<<<BT / 256, 256>>>(z);
    argmin_kernel<<<BT / TM, NTHREADS>>>(z, emb);
    gather_loss_kernel<<<512, 256>>>(z, emb, out);
    finalize_kernel<<<1, 256>>>(out);
}

// round 4
// speedup vs baseline: 1.8771x; 1.8771x over previous
#include <cuda_runtime.h>
#include <cuda_bf16.h>
#include <cstdint>

// ---------------------------------------------------------------------------
#define BT      16384
#define DDIM    512
#define NE      8192
#define BETA    0.25
#define KTOT    1536            // 3 concatenated bf16 planes

#define ZQ_ELEMS   (BT * DDIM)
#define LOSS_OFF   ZQ_ELEMS
#define IDX_OFF    (ZQ_ELEMS + 1)
#define VAR_OFF    (ZQ_ELEMS + 1 + BT)

#define M_TILE   128
#define N_TILE   256
#define N_TILES  (NE / N_TILE)            // 32
#define KC       64
#define KSTEPS   (KTOT / KC)              // 24 k-stages per n-tile
#define TOT_STAGES (N_TILES * KSTEPS)     // 768

#define A_BYTES  (M_TILE * 128)           // 16384
#define B_BYTES  (N_TILE * 128)           // 32768
#define STAGE_B  (A_BYTES + B_BYTES)      // 49152
#define SMEM_DYN (3 * STAGE_B)            // 147456

#define EPS_MARGIN 4e-4f
#define FINF __int_as_float(0x7f800000)

// ---------------------------------------------------------------------------
// Device scratch
// ---------------------------------------------------------------------------
__device__ __align__(256) __nv_bfloat16 g_zA[BT * KTOT];   // [z1 | z1 | z2]
__device__ __align__(256) __nv_bfloat16 g_eB[NE * KTOT];   // [e1 | e2 | e1]
__device__ float  g_zf2[BT];
__device__ float  g_en2[NE];
__device__ int    g_idx[BT];
__device__ double g_partial[512];
__device__ float  g_cd[BT * 48];   // per-row candidate d (16 slots x top-3)
__device__ int    g_ci[BT * 48];   // per-row candidate idx

// ---------------------------------------------------------------------------
__device__ __forceinline__ uint32_t smem_u32(const void* p) {
    uint32_t a;
    asm("{ .reg .u64 t; cvta.to.shared.u64 t, %1; cvt.u32.u64 %0, t; }"
        : "=r"(a) : "l"(p));
    return a;
}
__device__ __forceinline__ void cp16(uint32_t dst, const void* src) {
    asm volatile("cp.async.cg.shared.global [%0], [%1], 16;"
                 :: "r"(dst), "l"(src) : "memory");
}
__device__ __forceinline__ void ldm_x4(uint32_t* r, uint32_t addr) {
    asm volatile("ldmatrix.sync.aligned.m8n8.x4.shared.b16 {%0,%1,%2,%3}, [%4];"
                 : "=r"(r[0]), "=r"(r[1]), "=r"(r[2]), "=r"(r[3]) : "r"(addr));
}
__device__ __forceinline__ void hmma(float* c, const uint32_t* a,
                                     const uint32_t* b) {
    asm volatile(
        "mma.sync.aligned.m16n8k16.row.col.f32.bf16.bf16.f32 "
        "{%0,%1,%2,%3}, {%4,%5,%6,%7}, {%8,%9}, {%0,%1,%2,%3};"
        : "+f"(c[0]), "+f"(c[1]), "+f"(c[2]), "+f"(c[3])
        : "r"(a[0]), "r"(a[1]), "r"(a[2]), "r"(a[3]), "r"(b[0]), "r"(b[1]));
}

// ---------------------------------------------------------------------------
// Preprocessing
// ---------------------------------------------------------------------------
__global__ void zprep_kernel(const float* __restrict__ z) {
    int i = blockIdx.x * blockDim.x + threadIdx.x;
    float v = z[i];
    __nv_bfloat16 h = __float2bfloat16(v);
    float lo = v - __bfloat162float(h);
    int row = i >> 9, c = i & 511;
    size_t b = (size_t)row * KTOT + c;
    g_zA[b] = h;
    g_zA[b + 512] = h;
    g_zA[b + 1024] = __float2bfloat16(lo);
}
__global__ void eprep_kernel(const float* __restrict__ emb) {
    int i = blockIdx.x * blockDim.x + threadIdx.x;
    float v = emb[i];
    __nv_bfloat16 h = __float2bfloat16(v);
    float lo = v - __bfloat162float(h);
    int row = i >> 9, c = i & 511;
    size_t b = (size_t)row * KTOT + c;
    g_eB[b] = h;
    g_eB[b + 512] = __float2bfloat16(lo);
    g_eB[b + 1024] = h;
}
__global__ void en2_kernel(const float* __restrict__ emb) {
    int n = blockIdx.x * blockDim.x + threadIdx.x;
    const float* p = emb + (size_t)n * DDIM;
    float s = 0.0f;
    for (int k = 0; k < DDIM; k++) s = __fadd_rn(s, __fmul_rn(p[k], p[k]));
    g_en2[n] = s;
}
__global__ void zf2_kernel(const float* __restrict__ z) {
    int r = blockIdx.x * blockDim.x + threadIdx.x;
    const float* p = z + (size_t)r * DDIM;
    float s = 0.0f;
    for (int k = 0; k < DDIM; k++) s = __fadd_rn(s, __fmul_rn(p[k], p[k]));
    g_zf2[r] = s;
}

// ---------------------------------------------------------------------------
// Pass 1: fused split-bf16 GEMM + per-thread top-3 candidate tracking.
// ---------------------------------------------------------------------------
__global__ __launch_bounds__(512, 1) void vq_mma_kernel() {
    extern __shared__ __align__(1024) char dsm[];

    const int tid = threadIdx.x;
    const int l   = tid & 31;
    const int wid = tid >> 5;
    const int wm  = wid & 3;
    const int wn  = wid >> 2;
    const int rowBlock = blockIdx.x * M_TILE;
    const uint32_t sb = smem_u32(dsm);

    const int arow = l & 15;
    const int agr  = l >> 4;
    const int brow = (l & 7) | ((l >> 4) << 3);
    const int bgr  = (l >> 3) & 1;
    const uint32_t aoffL = (uint32_t)(wm * 32 + arow) * 128;
    const uint32_t boffL = (uint32_t)(wn * 64 + brow) * 128;
    const int aswz = arow & 7;
    const int bswz = l & 7;

    float acc[2][8][4];
    // top-3 candidate lists per row-slot (rs = mi*2 + h)
    float ld3[4][3];
    int   li3[4][3];
    float w3[4];
#pragma unroll
    for (int rs = 0; rs < 4; rs++) {
        w3[rs] = FINF;
#pragma unroll
        for (int j = 0; j < 3; j++) { ld3[rs][j] = FINF; li3[rs][j] = 0x7fffffff; }
    }

    auto load_stage = [&](int s) {
        if (s < TOT_STAGES) {
            const int nt  = s / KSTEPS;
            const int kcg = (s % KSTEPS) * KC;
            const uint32_t base = sb + (s % 3) * STAGE_B;
#pragma unroll
            for (int i = 0; i < 6; ++i) {
                const int seg = tid + i * 512;
                uint32_t dst;
                const __nv_bfloat16* src;
                if (seg < 1024) {
                    const int r = seg >> 3, gs = seg & 7;
                    dst = base + r * 128 + ((gs ^ (r & 7)) << 4);
                    src = g_zA + (size_t)(rowBlock + r) * KTOT + kcg + gs * 8;
                } else {
                    const int s2 = seg - 1024;
                    const int r = s2 >> 3, gs = s2 & 7;
                    dst = base + A_BYTES + r * 128 + ((gs ^ (r & 7)) << 4);
                    src = g_eB + (size_t)((s / KSTEPS) * N_TILE + r) * KTOT + kcg + gs * 8;
                }
                cp16(dst, src);
            }
        }
        asm volatile("cp.async.commit_group;" ::: "memory");
    };

    load_stage(0);
    load_stage(1);

    for (int s = 0; s < TOT_STAGES; ++s) {
        asm volatile("cp.async.wait_group 1;" ::: "memory");
        __syncthreads();
        load_stage(s + 2);

        const int kc = s % KSTEPS;
        if (kc == 0) {
#pragma unroll
            for (int mi = 0; mi < 2; mi++)
#pragma unroll
                for (int nj = 0; nj < 8; nj++)
#pragma unroll
                    for (int c = 0; c < 4; c++) acc[mi][nj][c] = 0.0f;
        }

        const uint32_t As = sb + (s % 3) * STAGE_B;
        const uint32_t Bs = As + A_BYTES;

#pragma unroll
        for (int ks = 0; ks < 4; ++ks) {
            uint32_t a[2][4], b[4][4];
#pragma unroll
            for (int mi = 0; mi < 2; mi++)
                ldm_x4(a[mi], As + aoffL + mi * (16 * 128)
                              + ((((ks * 2 + agr)) ^ aswz) << 4));
#pragma unroll
            for (int j = 0; j < 4; j++)
                ldm_x4(b[j], Bs + boffL + j * (16 * 128)
                             + ((((ks * 2 + bgr)) ^ bswz) << 4));
#pragma unroll
            for (int mi = 0; mi < 2; mi++)
#pragma unroll
                for (int nj = 0; nj < 8; nj++)
                    hmma(acc[mi][nj], a[mi], &b[nj >> 1][(nj & 1) * 2]);
        }

        // ---- per-n-tile epilogue: top-3 candidate tracking ----------------
        if (kc == KSTEPS - 1) {
            const int nb = (s / KSTEPS) * N_TILE + wn * 64 + 2 * (l & 3);
#pragma unroll
            for (int mi = 0; mi < 2; mi++) {
#pragma unroll
                for (int h = 0; h < 2; h++) {
                    const int rs = mi * 2 + h;
                    const float zf = g_zf2[rowBlock + wm * 32 + mi * 16
                                           + h * 8 + (l >> 2)];
#pragma unroll
                    for (int nj = 0; nj < 8; nj++) {
#pragma unroll
                        for (int c = 0; c < 2; c++) {
                            const int n = nb + nj * 8 + c;
                            const float e2 = __ldg(&g_en2[n]);
                            const float d = __fadd_rn(__fadd_rn(zf, e2),
                                            -2.0f * acc[mi][nj][h * 2 + c]);
                            if (d < w3[rs]) {
                                ld3[rs][2] = d; li3[rs][2] = n;
                                if (ld3[rs][2] < ld3[rs][1]) {
                                    float td = ld3[rs][2]; ld3[rs][2] = ld3[rs][1]; ld3[rs][1] = td;
                                    int ti = li3[rs][2]; li3[rs][2] = li3[rs][1]; li3[rs][1] = ti;
                                }
                                if (ld3[rs][1] < ld3[rs][0]) {
                                    float td = ld3[rs][1]; ld3[rs][1] = ld3[rs][0]; ld3[rs][0] = td;
                                    int ti = li3[rs][1]; li3[rs][1] = li3[rs][0]; li3[rs][0] = ti;
                                }
                                w3[rs] = ld3[rs][2];
                            }
                        }
                    }
                }
            }
        }
    }
    asm volatile("cp.async.wait_group 0;" ::: "memory");

    // ---- write candidate lists to global ----------------------------------
#pragma unroll
    for (int rs = 0; rs < 4; rs++) {
        const int mi = rs >> 1, h = rs & 1;
        const int row = rowBlock + wm * 32 + mi * 16 + h * 8 + (l >> 2);
        const int slot = wn * 4 + (l & 3);
        const int base = row * 48 + slot * 3;
#pragma unroll
        for (int j = 0; j < 3; j++) {
            g_cd[base + j] = ld3[rs][j];
            g_ci[base + j] = li3[rs][j];
        }
    }
}

// ---------------------------------------------------------------------------
// Pass 2: exact fp32 refinement of candidates (bit-identical to R1 numerics).
// One warp per row.
// ---------------------------------------------------------------------------
__global__ __launch_bounds__(256) void refine_kernel(const float* __restrict__ z,
                                                     const float* __restrict__ emb) {
    const int row  = (blockIdx.x * blockDim.x + threadIdx.x) >> 5;
    const int lane = threadIdx.x & 31;
    const int base = row * 48;

    float da = g_cd[base + lane];
    int   ia = g_ci[base + lane];
    float db = (lane < 16) ? g_cd[base + 32 + lane] : FINF;
    int   ib = (lane < 16) ? g_ci[base + 32 + lane] : 0x7fffffff;

    // global approx min over the 48 entries
    float m = fminf(da, db);
#pragma unroll
    for (int off = 16; off > 0; off >>= 1)
        m = fminf(m, __shfl_xor_sync(0xffffffffu, m, off));
    const float thr = m + EPS_MARGIN;

    const float* zp = z + (size_t)row * DDIM;
    const float zf2 = g_zf2[row];

    float fa = FINF, fb = FINF;
    if (da <= thr) {
        const float* ep = emb + (size_t)ia * DDIM;
        float acc = 0.0f;
        for (int k = 0; k < DDIM; k++) acc = fmaf(zp[k], ep[k], acc);
        fa = __fadd_rn(__fadd_rn(zf2, g_en2[ia]), -2.0f * acc);
    } else ia = 0x7fffffff;
    if (db <= thr) {
        const float* ep = emb + (size_t)ib * DDIM;
        float acc = 0.0f;
        for (int k = 0; k < DDIM; k++) acc = fmaf(zp[k], ep[k], acc);
        fb = __fadd_rn(__fadd_rn(zf2, g_en2[ib]), -2.0f * acc);
    } else ib = 0x7fffffff;

    float bd = fa; int bi = ia;
    if (fb < bd || (fb == bd && ib < bi)) { bd = fb; bi = ib; }
#pragma unroll
    for (int off = 16; off > 0; off >>= 1) {
        float od = __shfl_xor_sync(0xffffffffu, bd, off);
        int   oi = __shfl_xor_sync(0xffffffffu, bi, off);
        if (od < bd || (od == bd && oi < bi)) { bd = od; bi = oi; }
    }
    if (lane == 0) g_idx[row] = bi;
}

// ---------------------------------------------------------------------------
__global__ void gather_loss_kernel(const float* __restrict__ z,
                                   const float* __restrict__ emb,
                                   float* __restrict__ out) {
    __shared__ double red[256];
    const int bid = blockIdx.x;
    const int base4 = bid * 4096;
    double s = 0.0;
#pragma unroll 4
    for (int it = 0; it < 16; ++it) {
        const int g = base4 + it * 256 + threadIdx.x;
        const int row = g >> 7;
        const int k4  = g & 127;
        float4 v = *reinterpret_cast<const float4*>(
            emb + (size_t)g_idx[row] * DDIM + k4 * 4);
        *reinterpret_cast<float4*>(out + (size_t)g * 4) = v;
        float4 zz = *reinterpret_cast<const float4*>(z + (size_t)g * 4);
        float dx = v.x - zz.x, dy = v.y - zz.y;
        float dz = v.z - zz.z, dw = v.w - zz.w;
        s += (double)dx * dx + (double)dy * dy + (double)dz * dz + (double)dw * dw;
    }
    red[threadIdx.x] = s;
    __syncthreads();
    for (int off = 128; off > 0; off >>= 1) {
        if (threadIdx.x < off) red[threadIdx.x] += red[threadIdx.x + off];
        __syncthreads();
    }
    if (threadIdx.x == 0) g_partial[bid] = red[0];
}

__global__ void finalize_kernel(float* __restrict__ out) {
    __shared__ double rs[256], rs2[256];
    double s = 0.0, s2 = 0.0;
    for (int i = threadIdx.x; i < BT; i += 256) {
        int iv = g_idx[i];
        out[IDX_OFF + i] = (float)iv;
        double dv = (double)iv;
        s += dv; s2 += dv * dv;
    }
    rs[threadIdx.x] = s; rs2[threadIdx.x] = s2;
    __syncthreads();
    for (int off = 128; off > 0; off >>= 1) {
        if (threadIdx.x < off) {
            rs[threadIdx.x]  += rs[threadIdx.x + off];
            rs2[threadIdx.x] += rs2[threadIdx.x + off];
        }
        __syncthreads();
    }
    if (threadIdx.x == 0) {
        double ls = 0.0;
        for (int i = 0; i < 512; i++) ls += g_partial[i];
        double mse = ls / (double)ZQ_ELEMS;
        out[LOSS_OFF] = (float)((1.0 + BETA) * mse);
        double mean = rs[0] / (double)BT;
        out[VAR_OFF] = (float)(rs2[0] / (double)BT - mean * mean);
    }
}

// ---------------------------------------------------------------------------
extern "C" void kernel_launch(void* const* d_in, const int* in_sizes, int n_in,
                              void* d_out, int out_size) {
    const float* z   = (const float*)d_in[0];
    const float* emb = (const float*)d_in[1];
    float* out = (float*)d_out;

    cudaFuncSetAttribute(vq_mma_kernel,
                         cudaFuncAttributeMaxDynamicSharedMemorySize, SMEM_DYN);

    zprep_kernel<<<ZQ_ELEMS / 256, 256>>>(z);
    eprep_kernel<<<NE * DDIM / 256, 256>>>(emb);
    en2_kernel<<<NE / 256, 256>>>(emb);
    zf2_kernel<<<BT / 256, 256>>>(z);
    vq_mma_kernel<<<BT / M_TILE, 512, SMEM_DYN>>>();
    refine_kernel<<<BT * 32 / 256, 256>>>(z, emb);
    gather_loss_kernel<<<512, 256>>>(z, emb, out);
    finalize_kernel<<<1, 256>>>(out);
}

// round 7
// speedup vs baseline: 3.5552x; 1.8940x over previous
#include <cuda_runtime.h>
#include <cuda_bf16.h>
#include <cstdint>

// ---------------------------------------------------------------------------
#define BT      16384
#define DDIM    512
#define NE      8192
#define BETA    0.25
#define KTOT    512             // single bf16 hi plane; exact refine fixes errors

#define ZQ_ELEMS   (BT * DDIM)
#define LOSS_OFF   ZQ_ELEMS
#define IDX_OFF    (ZQ_ELEMS + 1)
#define VAR_OFF    (ZQ_ELEMS + 1 + BT)

#define M_TILE   128
#define N_TILE   256
#define N_TILES  (NE / N_TILE)            // 32
#define KC       64
#define KSTEPS   (KTOT / KC)              // 8
#define TOT_STAGES (N_TILES * KSTEPS)     // 256

#define A_BYTES  (M_TILE * 128)           // 16384
#define B_BYTES  (N_TILE * 128)           // 32768
#define STAGE_B  (A_BYTES + B_BYTES)      // 49152
#define NSTG     4
#define SMEM_DYN (NSTG * STAGE_B)         // 196608

#define EPS_MARGIN 2e-3f
#define FINF __int_as_float(0x7f800000)

// ---------------------------------------------------------------------------
// Device scratch
// ---------------------------------------------------------------------------
__device__ __align__(256) __nv_bfloat16 g_zA[BT * KTOT];   // hi(z)
__device__ __align__(256) __nv_bfloat16 g_eB[NE * KTOT];   // hi(emb)
__device__ float  g_zf2[BT];
__device__ float  g_en2[NE];
__device__ int    g_idx[BT];
__device__ double g_partial[512];
__device__ float  g_cd[BT * 48];   // per-row candidates (16 slots x top-3)
__device__ int    g_ci[BT * 48];

// ---------------------------------------------------------------------------
__device__ __forceinline__ uint32_t smem_u32(const void* p) {
    uint32_t a;
    asm("{ .reg .u64 t; cvta.to.shared.u64 t, %1; cvt.u32.u64 %0, t; }"
        : "=r"(a) : "l"(p));
    return a;
}
__device__ __forceinline__ void cp16(uint32_t dst, const void* src) {
    asm volatile("cp.async.cg.shared.global [%0], [%1], 16;"
                 :: "r"(dst), "l"(src) : "memory");
}
__device__ __forceinline__ void ldm_x4(uint32_t* r, uint32_t addr) {
    asm volatile("ldmatrix.sync.aligned.m8n8.x4.shared.b16 {%0,%1,%2,%3}, [%4];"
                 : "=r"(r[0]), "=r"(r[1]), "=r"(r[2]), "=r"(r[3]) : "r"(addr));
}
__device__ __forceinline__ void hmma(float* c, const uint32_t* a,
                                     const uint32_t* b) {
    asm volatile(
        "mma.sync.aligned.m16n8k16.row.col.f32.bf16.bf16.f32 "
        "{%0,%1,%2,%3}, {%4,%5,%6,%7}, {%8,%9}, {%0,%1,%2,%3};"
        : "+f"(c[0]), "+f"(c[1]), "+f"(c[2]), "+f"(c[3])
        : "r"(a[0]), "r"(a[1]), "r"(a[2]), "r"(a[3]), "r"(b[0]), "r"(b[1]));
}

// ---------------------------------------------------------------------------
// Preprocessing: bf16 hi-plane (vectorized x4, flat layout)
// ---------------------------------------------------------------------------
__global__ void zprep_kernel(const float* __restrict__ z) {
    int i = blockIdx.x * blockDim.x + threadIdx.x;   // float4 index
    float4 v = reinterpret_cast<const float4*>(z)[i];
    __nv_bfloat162 a = {__float2bfloat16(v.x), __float2bfloat16(v.y)};
    __nv_bfloat162 b = {__float2bfloat16(v.z), __float2bfloat16(v.w)};
    reinterpret_cast<__nv_bfloat162*>(g_zA)[2 * i]     = a;
    reinterpret_cast<__nv_bfloat162*>(g_zA)[2 * i + 1] = b;
}
__global__ void eprep_kernel(const float* __restrict__ emb) {
    int i = blockIdx.x * blockDim.x + threadIdx.x;
    float4 v = reinterpret_cast<const float4*>(emb)[i];
    __nv_bfloat162 a = {__float2bfloat16(v.x), __float2bfloat16(v.y)};
    __nv_bfloat162 b = {__float2bfloat16(v.z), __float2bfloat16(v.w)};
    reinterpret_cast<__nv_bfloat162*>(g_eB)[2 * i]     = a;
    reinterpret_cast<__nv_bfloat162*>(g_eB)[2 * i + 1] = b;
}

// ---------------------------------------------------------------------------
// Row norms. Coalesced smem staging; accumulation in EXACT serial k order
// (bit-identical to R1/R4 norms). Output selected by TEMPLATE PARAM and
// written to the __device__ symbol FROM DEVICE CODE — never pass __device__
// symbols as host-side kernel args (that was the R5/R6 silent-zero bug).
// ---------------------------------------------------------------------------
template <int WHICH>   // 0 -> g_en2 (emb), 1 -> g_zf2 (z)
__global__ void norm_kernel(const float* __restrict__ x) {
    __shared__ float buf[128][65];
    const int r0 = blockIdx.x * 128;
    float s = 0.0f;
    for (int kc = 0; kc < DDIM; kc += 64) {
        __syncthreads();
#pragma unroll
        for (int i = 0; i < 16; ++i) {
            const int seg = threadIdx.x + i * 128;
            const int r = seg >> 4, c4 = seg & 15;
            float4 v = *reinterpret_cast<const float4*>(
                x + (size_t)(r0 + r) * DDIM + kc + c4 * 4);
            buf[r][c4 * 4 + 0] = v.x; buf[r][c4 * 4 + 1] = v.y;
            buf[r][c4 * 4 + 2] = v.z; buf[r][c4 * 4 + 3] = v.w;
        }
        __syncthreads();
#pragma unroll
        for (int k = 0; k < 64; ++k) {
            float q = __fmul_rn(buf[threadIdx.x][k], buf[threadIdx.x][k]);
            s = __fadd_rn(s, q);
        }
    }
    if (WHICH) g_zf2[r0 + threadIdx.x] = s;
    else       g_en2[r0 + threadIdx.x] = s;
}

// ---------------------------------------------------------------------------
// Pass 1: bf16 hi-plane GEMM + per-thread top-3 candidate tracking.
// 4-stage cp.async ring, 3-ahead prefetch.
// ---------------------------------------------------------------------------
__global__ __launch_bounds__(512, 1) void vq_mma_kernel() {
    extern __shared__ __align__(1024) char dsm[];

    const int tid = threadIdx.x;
    const int l   = tid & 31;
    const int wid = tid >> 5;
    const int wm  = wid & 3;
    const int wn  = wid >> 2;
    const int rowBlock = blockIdx.x * M_TILE;
    const uint32_t sb = smem_u32(dsm);

    const int arow = l & 15;
    const int agr  = l >> 4;
    const int brow = (l & 7) | ((l >> 4) << 3);
    const int bgr  = (l >> 3) & 1;
    const uint32_t aoffL = (uint32_t)(wm * 32 + arow) * 128;
    const uint32_t boffL = (uint32_t)(wn * 64 + brow) * 128;
    const int aswz = arow & 7;
    const int bswz = l & 7;

    float acc[2][8][4];
    float ld3[4][3];
    int   li3[4][3];
    float w3[4];
#pragma unroll
    for (int rs = 0; rs < 4; rs++) {
        w3[rs] = FINF;
#pragma unroll
        for (int j = 0; j < 3; j++) { ld3[rs][j] = FINF; li3[rs][j] = 0x7fffffff; }
    }

    auto load_stage = [&](int s) {
        if (s < TOT_STAGES) {
            const int kcg = (s % KSTEPS) * KC;
            const uint32_t base = sb + (s % NSTG) * STAGE_B;
#pragma unroll
            for (int i = 0; i < 6; ++i) {
                const int seg = tid + i * 512;
                uint32_t dst;
                const __nv_bfloat16* src;
                if (seg < 1024) {
                    const int r = seg >> 3, gs = seg & 7;
                    dst = base + r * 128 + ((gs ^ (r & 7)) << 4);
                    src = g_zA + (size_t)(rowBlock + r) * KTOT + kcg + gs * 8;
                } else {
                    const int s2 = seg - 1024;
                    const int r = s2 >> 3, gs = s2 & 7;
                    dst = base + A_BYTES + r * 128 + ((gs ^ (r & 7)) << 4);
                    src = g_eB + (size_t)((s / KSTEPS) * N_TILE + r) * KTOT + kcg + gs * 8;
                }
                cp16(dst, src);
            }
        }
        asm volatile("cp.async.commit_group;" ::: "memory");
    };

    load_stage(0);
    load_stage(1);
    load_stage(2);

    for (int s = 0; s < TOT_STAGES; ++s) {
        __syncthreads();                 // all warps done reading buf[(s+3)%4]
        load_stage(s + 3);               // prefetch 3 ahead
        asm volatile("cp.async.wait_group 3;" ::: "memory");  // stage s landed
        __syncthreads();

        const int kc = s % KSTEPS;
        if (kc == 0) {
#pragma unroll
            for (int mi = 0; mi < 2; mi++)
#pragma unroll
                for (int nj = 0; nj < 8; nj++)
#pragma unroll
                    for (int c = 0; c < 4; c++) acc[mi][nj][c] = 0.0f;
        }

        const uint32_t As = sb + (s % NSTG) * STAGE_B;
        const uint32_t Bs = As + A_BYTES;

#pragma unroll
        for (int ks = 0; ks < 4; ++ks) {
            uint32_t a[2][4], b[4][4];
#pragma unroll
            for (int mi = 0; mi < 2; mi++)
                ldm_x4(a[mi], As + aoffL + mi * (16 * 128)
                              + ((((ks * 2 + agr)) ^ aswz) << 4));
#pragma unroll
            for (int j = 0; j < 4; j++)
                ldm_x4(b[j], Bs + boffL + j * (16 * 128)
                             + ((((ks * 2 + bgr)) ^ bswz) << 4));
#pragma unroll
            for (int mi = 0; mi < 2; mi++)
#pragma unroll
                for (int nj = 0; nj < 8; nj++)
                    hmma(acc[mi][nj], a[mi], &b[nj >> 1][(nj & 1) * 2]);
        }

        // ---- per-n-tile epilogue: top-3 candidate tracking ----------------
        if (kc == KSTEPS - 1) {
            const int nb = (s / KSTEPS) * N_TILE + wn * 64 + 2 * (l & 3);
#pragma unroll
            for (int mi = 0; mi < 2; mi++) {
#pragma unroll
                for (int h = 0; h < 2; h++) {
                    const int rs = mi * 2 + h;
                    const float zf = g_zf2[rowBlock + wm * 32 + mi * 16
                                           + h * 8 + (l >> 2)];
#pragma unroll
                    for (int nj = 0; nj < 8; nj++) {
#pragma unroll
                        for (int c = 0; c < 2; c++) {
                            const int n = nb + nj * 8 + c;
                            const float e2 = __ldg(&g_en2[n]);
                            const float d = __fadd_rn(__fadd_rn(zf, e2),
                                            -2.0f * acc[mi][nj][h * 2 + c]);
                            if (d < w3[rs]) {
                                ld3[rs][2] = d; li3[rs][2] = n;
                                if (ld3[rs][2] < ld3[rs][1]) {
                                    float td = ld3[rs][2]; ld3[rs][2] = ld3[rs][1]; ld3[rs][1] = td;
                                    int ti = li3[rs][2]; li3[rs][2] = li3[rs][1]; li3[rs][1] = ti;
                                }
                                if (ld3[rs][1] < ld3[rs][0]) {
                                    float td = ld3[rs][1]; ld3[rs][1] = ld3[rs][0]; ld3[rs][0] = td;
                                    int ti = li3[rs][1]; li3[rs][1] = li3[rs][0]; li3[rs][0] = ti;
                                }
                                w3[rs] = ld3[rs][2];
                            }
                        }
                    }
                }
            }
        }
    }
    asm volatile("cp.async.wait_group 0;" ::: "memory");

#pragma unroll
    for (int rs = 0; rs < 4; rs++) {
        const int mi = rs >> 1, h = rs & 1;
        const int row = rowBlock + wm * 32 + mi * 16 + h * 8 + (l >> 2);
        const int slot = wn * 4 + (l & 3);
        const int base = row * 48 + slot * 3;
#pragma unroll
        for (int j = 0; j < 3; j++) {
            g_cd[base + j] = ld3[rs][j];
            g_ci[base + j] = li3[rs][j];
        }
    }
}

// ---------------------------------------------------------------------------
// Pass 2: exact fp32 refinement (bit-identical to R1 numerics). Warp per row.
// ---------------------------------------------------------------------------
__global__ __launch_bounds__(256) void refine_kernel(const float* __restrict__ z,
                                                     const float* __restrict__ emb) {
    const int row  = (blockIdx.x * blockDim.x + threadIdx.x) >> 5;
    const int lane = threadIdx.x & 31;
    const int base = row * 48;

    float da = g_cd[base + lane];
    int   ia = g_ci[base + lane];
    float db = (lane < 16) ? g_cd[base + 32 + lane] : FINF;
    int   ib = (lane < 16) ? g_ci[base + 32 + lane] : 0x7fffffff;

    float m = fminf(da, db);
#pragma unroll
    for (int off = 16; off > 0; off >>= 1)
        m = fminf(m, __shfl_xor_sync(0xffffffffu, m, off));
    const float thr = m + EPS_MARGIN;

    const float* zp = z + (size_t)row * DDIM;
    const float zf2 = g_zf2[row];

    float fa = FINF, fb = FINF;
    if (da <= thr) {
        const float* ep = emb + (size_t)ia * DDIM;
        float acc = 0.0f;
        for (int k = 0; k < DDIM; k++) acc = fmaf(zp[k], ep[k], acc);
        fa = __fadd_rn(__fadd_rn(zf2, g_en2[ia]), -2.0f * acc);
    } else ia = 0x7fffffff;
    if (db <= thr) {
        const float* ep = emb + (size_t)ib * DDIM;
        float acc = 0.0f;
        for (int k = 0; k < DDIM; k++) acc = fmaf(zp[k], ep[k], acc);
        fb = __fadd_rn(__fadd_rn(zf2, g_en2[ib]), -2.0f * acc);
    } else ib = 0x7fffffff;

    float bd = fa; int bi = ia;
    if (fb < bd || (fb == bd && ib < bi)) { bd = fb; bi = ib; }
#pragma unroll
    for (int off = 16; off > 0; off >>= 1) {
        float od = __shfl_xor_sync(0xffffffffu, bd, off);
        int   oi = __shfl_xor_sync(0xffffffffu, bi, off);
        if (od < bd || (od == bd && oi < bi)) { bd = od; bi = oi; }
    }
    if (lane == 0) g_idx[row] = bi;
}

// ---------------------------------------------------------------------------
__global__ void gather_loss_kernel(const float* __restrict__ z,
                                   const float* __restrict__ emb,
                                   float* __restrict__ out) {
    __shared__ double red[256];
    const int bid = blockIdx.x;
    const int base4 = bid * 4096;
    double s = 0.0;
#pragma unroll 4
    for (int it = 0; it < 16; ++it) {
        const int g = base4 + it * 256 + threadIdx.x;
        const int row = g >> 7;
        const int k4  = g & 127;
        float4 v = *reinterpret_cast<const float4*>(
            emb + (size_t)g_idx[row] * DDIM + k4 * 4);
        *reinterpret_cast<float4*>(out + (size_t)g * 4) = v;
        float4 zz = *reinterpret_cast<const float4*>(z + (size_t)g * 4);
        float dx = v.x - zz.x, dy = v.y - zz.y;
        float dz = v.z - zz.z, dw = v.w - zz.w;
        s += (double)dx * dx + (double)dy * dy + (double)dz * dz + (double)dw * dw;
    }
    red[threadIdx.x] = s;
    __syncthreads();
    for (int off = 128; off > 0; off >>= 1) {
        if (threadIdx.x < off) red[threadIdx.x] += red[threadIdx.x + off];
        __syncthreads();
    }
    if (threadIdx.x == 0) g_partial[bid] = red[0];
}

__global__ void finalize_kernel(float* __restrict__ out) {
    __shared__ double rs[256], rs2[256];
    double s = 0.0, s2 = 0.0;
    for (int i = threadIdx.x; i < BT; i += 256) {
        int iv = g_idx[i];
        out[IDX_OFF + i] = (float)iv;
        double dv = (double)iv;
        s += dv; s2 += dv * dv;
    }
    rs[threadIdx.x] = s; rs2[threadIdx.x] = s2;
    __syncthreads();
    for (int off = 128; off > 0; off >>= 1) {
        if (threadIdx.x < off) {
            rs[threadIdx.x]  += rs[threadIdx.x + off];
            rs2[threadIdx.x] += rs2[threadIdx.x + off];
        }
        __syncthreads();
    }
    if (threadIdx.x == 0) {
        double ls = 0.0;
        for (int i = 0; i < 512; i++) ls += g_partial[i];
        double mse = ls / (double)ZQ_ELEMS;
        out[LOSS_OFF] = (float)((1.0 + BETA) * mse);
        double mean = rs[0] / (double)BT;
        out[VAR_OFF] = (float)(rs2[0] / (double)BT - mean * mean);
    }
}

// ---------------------------------------------------------------------------
extern "C" void kernel_launch(void* const* d_in, const int* in_sizes, int n_in,
                              void* d_out, int out_size) {
    const float* z   = (const float*)d_in[0];
    const float* emb = (const float*)d_in[1];
    float* out = (float*)d_out;

    cudaFuncSetAttribute(vq_mma_kernel,
                         cudaFuncAttributeMaxDynamicSharedMemorySize, SMEM_DYN);

    zprep_kernel<<<ZQ_ELEMS / 4 / 256, 256>>>(z);
    eprep_kernel<<<NE * DDIM / 4 / 256, 256>>>(emb);
    norm_kernel<0><<<NE / 128, 128>>>(emb);   // -> g_en2 (device-side write)
    norm_kernel<1><<<BT / 128, 128>>>(z);     // -> g_zf2 (device-side write)
    vq_mma_kernel<<<BT / M_TILE, 512, SMEM_DYN>>>();
    refine_kernel<<<BT * 32 / 256, 256>>>(z, emb);
    gather_loss_kernel<<<512, 256>>>(z, emb, out);
    finalize_kernel<<<1, 256>>>(out);
}

// round 8
// speedup vs baseline: 3.6905x; 1.0380x over previous
#include <cuda_runtime.h>
#include <cuda_bf16.h>
#include <cstdint>

// ---------------------------------------------------------------------------
#define BT      16384
#define DDIM    512
#define NE      8192
#define BETA    0.25
#define KTOT    512             // single bf16 hi plane; exact refine fixes errors

#define ZQ_ELEMS   (BT * DDIM)
#define LOSS_OFF   ZQ_ELEMS
#define IDX_OFF    (ZQ_ELEMS + 1)
#define VAR_OFF    (ZQ_ELEMS + 1 + BT)

#define M_TILE   128
#define N_TILE   256
#define N_TILES  (NE / N_TILE)            // 32
#define KC       64
#define KSTEPS   (KTOT / KC)              // 8
#define TOT_STAGES (N_TILES * KSTEPS)     // 256

#define A_BYTES  (M_TILE * 128)           // 16384
#define B_BYTES  (N_TILE * 128)           // 32768
#define STAGE_B  (A_BYTES + B_BYTES)      // 49152
#define NSTG     4
#define SMEM_DYN (NSTG * STAGE_B)         // 196608

#define EPS_MARGIN 2e-3f
#define FINF __int_as_float(0x7f800000)

// ---------------------------------------------------------------------------
// Device scratch
// ---------------------------------------------------------------------------
__device__ __align__(256) __nv_bfloat16 g_zA[BT * KTOT];   // hi(z)
__device__ __align__(256) __nv_bfloat16 g_eB[NE * KTOT];   // hi(emb)
__device__ float  g_zf2[BT];
__device__ float  g_en2[NE];
__device__ int    g_idx[BT];
__device__ double g_partial[1024];
__device__ float  g_cd[BT * 48];   // per-row candidates (16 slots x top-3)
__device__ int    g_ci[BT * 48];

// ---------------------------------------------------------------------------
__device__ __forceinline__ uint32_t smem_u32(const void* p) {
    uint32_t a;
    asm("{ .reg .u64 t; cvta.to.shared.u64 t, %1; cvt.u32.u64 %0, t; }"
        : "=r"(a) : "l"(p));
    return a;
}
__device__ __forceinline__ void cp16(uint32_t dst, const void* src) {
    asm volatile("cp.async.cg.shared.global [%0], [%1], 16;"
                 :: "r"(dst), "l"(src) : "memory");
}
__device__ __forceinline__ void ldm_x4(uint32_t* r, uint32_t addr) {
    asm volatile("ldmatrix.sync.aligned.m8n8.x4.shared.b16 {%0,%1,%2,%3}, [%4];"
                 : "=r"(r[0]), "=r"(r[1]), "=r"(r[2]), "=r"(r[3]) : "r"(addr));
}
__device__ __forceinline__ void hmma(float* c, const uint32_t* a,
                                     const uint32_t* b) {
    asm volatile(
        "mma.sync.aligned.m16n8k16.row.col.f32.bf16.bf16.f32 "
        "{%0,%1,%2,%3}, {%4,%5,%6,%7}, {%8,%9}, {%0,%1,%2,%3};"
        : "+f"(c[0]), "+f"(c[1]), "+f"(c[2]), "+f"(c[3])
        : "r"(a[0]), "r"(a[1]), "r"(a[2]), "r"(a[3]), "r"(b[0]), "r"(b[1]));
}

// ---------------------------------------------------------------------------
// Preprocessing: bf16 hi-plane (vectorized x4, flat layout)
// ---------------------------------------------------------------------------
__global__ void zprep_kernel(const float* __restrict__ z) {
    int i = blockIdx.x * blockDim.x + threadIdx.x;   // float4 index
    float4 v = reinterpret_cast<const float4*>(z)[i];
    __nv_bfloat162 a = {__float2bfloat16(v.x), __float2bfloat16(v.y)};
    __nv_bfloat162 b = {__float2bfloat16(v.z), __float2bfloat16(v.w)};
    reinterpret_cast<__nv_bfloat162*>(g_zA)[2 * i]     = a;
    reinterpret_cast<__nv_bfloat162*>(g_zA)[2 * i + 1] = b;
}
__global__ void eprep_kernel(const float* __restrict__ emb) {
    int i = blockIdx.x * blockDim.x + threadIdx.x;
    float4 v = reinterpret_cast<const float4*>(emb)[i];
    __nv_bfloat162 a = {__float2bfloat16(v.x), __float2bfloat16(v.y)};
    __nv_bfloat162 b = {__float2bfloat16(v.z), __float2bfloat16(v.w)};
    reinterpret_cast<__nv_bfloat162*>(g_eB)[2 * i]     = a;
    reinterpret_cast<__nv_bfloat162*>(g_eB)[2 * i + 1] = b;
}

// ---------------------------------------------------------------------------
// Merged row norms (emb blocks [0,64), z blocks [64,192)). Accumulation kept
// in EXACT serial k order per row (bit-identical to R1/R4/R7; refine depends
// on it). Writes __device__ symbols from device code ONLY (R5/R6 lesson).
// Merged so vq_mma sits at launch index 3 (the one ncu captures).
// ---------------------------------------------------------------------------
__global__ void norms_kernel(const float* __restrict__ emb,
                             const float* __restrict__ z) {
    __shared__ float buf[128][65];
    const bool is_z = blockIdx.x >= (NE / 128);
    const float* x = is_z ? z : emb;
    const int r0 = (is_z ? (blockIdx.x - NE / 128) : blockIdx.x) * 128;
    float s = 0.0f;
    for (int kc = 0; kc < DDIM; kc += 64) {
        __syncthreads();
#pragma unroll
        for (int i = 0; i < 16; ++i) {
            const int seg = threadIdx.x + i * 128;
            const int r = seg >> 4, c4 = seg & 15;
            float4 v = *reinterpret_cast<const float4*>(
                x + (size_t)(r0 + r) * DDIM + kc + c4 * 4);
            buf[r][c4 * 4 + 0] = v.x; buf[r][c4 * 4 + 1] = v.y;
            buf[r][c4 * 4 + 2] = v.z; buf[r][c4 * 4 + 3] = v.w;
        }
        __syncthreads();
#pragma unroll
        for (int k = 0; k < 64; ++k) {
            float q = __fmul_rn(buf[threadIdx.x][k], buf[threadIdx.x][k]);
            s = __fadd_rn(s, q);
        }
    }
    if (is_z) g_zf2[r0 + threadIdx.x] = s;
    else      g_en2[r0 + threadIdx.x] = s;
}

// ---------------------------------------------------------------------------
// Pass 1: bf16 hi-plane GEMM + per-thread top-3 candidate tracking.
// 4-buffer cp.async ring, prefetch distance 2, ONE __syncthreads per stage:
//   buffer (s+2)%4 was last read at stage s-2; the stage s-1 barrier already
//   orders those reads before this stage's writes.
// ---------------------------------------------------------------------------
__global__ __launch_bounds__(512, 1) void vq_mma_kernel() {
    extern __shared__ __align__(1024) char dsm[];

    const int tid = threadIdx.x;
    const int l   = tid & 31;
    const int wid = tid >> 5;
    const int wm  = wid & 3;
    const int wn  = wid >> 2;
    const int rowBlock = blockIdx.x * M_TILE;
    const uint32_t sb = smem_u32(dsm);

    const int arow = l & 15;
    const int agr  = l >> 4;
    const int brow = (l & 7) | ((l >> 4) << 3);
    const int bgr  = (l >> 3) & 1;
    const uint32_t aoffL = (uint32_t)(wm * 32 + arow) * 128;
    const uint32_t boffL = (uint32_t)(wn * 64 + brow) * 128;
    const int aswz = arow & 7;
    const int bswz = l & 7;

    float acc[2][8][4];
    float ld3[4][3];
    int   li3[4][3];
    float w3[4];
#pragma unroll
    for (int rs = 0; rs < 4; rs++) {
        w3[rs] = FINF;
#pragma unroll
        for (int j = 0; j < 3; j++) { ld3[rs][j] = FINF; li3[rs][j] = 0x7fffffff; }
    }

    auto load_stage = [&](int s) {
        if (s < TOT_STAGES) {
            const int kcg = (s % KSTEPS) * KC;
            const uint32_t base = sb + (s % NSTG) * STAGE_B;
#pragma unroll
            for (int i = 0; i < 6; ++i) {
                const int seg = tid + i * 512;
                uint32_t dst;
                const __nv_bfloat16* src;
                if (seg < 1024) {
                    const int r = seg >> 3, gs = seg & 7;
                    dst = base + r * 128 + ((gs ^ (r & 7)) << 4);
                    src = g_zA + (size_t)(rowBlock + r) * KTOT + kcg + gs * 8;
                } else {
                    const int s2 = seg - 1024;
                    const int r = s2 >> 3, gs = s2 & 7;
                    dst = base + A_BYTES + r * 128 + ((gs ^ (r & 7)) << 4);
                    src = g_eB + (size_t)((s / KSTEPS) * N_TILE + r) * KTOT + kcg + gs * 8;
                }
                cp16(dst, src);
            }
        }
        asm volatile("cp.async.commit_group;" ::: "memory");
    };

    load_stage(0);
    load_stage(1);

    for (int s = 0; s < TOT_STAGES; ++s) {
        load_stage(s + 2);               // prefetch 2 ahead (distinct buffer)
        asm volatile("cp.async.wait_group 2;" ::: "memory");  // stage s landed
        __syncthreads();                 // single barrier per stage

        const int kc = s % KSTEPS;
        if (kc == 0) {
#pragma unroll
            for (int mi = 0; mi < 2; mi++)
#pragma unroll
                for (int nj = 0; nj < 8; nj++)
#pragma unroll
                    for (int c = 0; c < 4; c++) acc[mi][nj][c] = 0.0f;
        }

        const uint32_t As = sb + (s % NSTG) * STAGE_B;
        const uint32_t Bs = As + A_BYTES;

#pragma unroll
        for (int ks = 0; ks < 4; ++ks) {
            uint32_t a[2][4], b[4][4];
#pragma unroll
            for (int mi = 0; mi < 2; mi++)
                ldm_x4(a[mi], As + aoffL + mi * (16 * 128)
                              + ((((ks * 2 + agr)) ^ aswz) << 4));
#pragma unroll
            for (int j = 0; j < 4; j++)
                ldm_x4(b[j], Bs + boffL + j * (16 * 128)
                             + ((((ks * 2 + bgr)) ^ bswz) << 4));
#pragma unroll
            for (int mi = 0; mi < 2; mi++)
#pragma unroll
                for (int nj = 0; nj < 8; nj++)
                    hmma(acc[mi][nj], a[mi], &b[nj >> 1][(nj & 1) * 2]);
        }

        // ---- per-n-tile epilogue: top-3 candidate tracking ----------------
        if (kc == KSTEPS - 1) {
            const int nb = (s / KSTEPS) * N_TILE + wn * 64 + 2 * (l & 3);
#pragma unroll
            for (int mi = 0; mi < 2; mi++) {
#pragma unroll
                for (int h = 0; h < 2; h++) {
                    const int rs = mi * 2 + h;
                    const float zf = g_zf2[rowBlock + wm * 32 + mi * 16
                                           + h * 8 + (l >> 2)];
#pragma unroll
                    for (int nj = 0; nj < 8; nj++) {
#pragma unroll
                        for (int c = 0; c < 2; c++) {
                            const int n = nb + nj * 8 + c;
                            const float e2 = __ldg(&g_en2[n]);
                            const float d = __fadd_rn(__fadd_rn(zf, e2),
                                            -2.0f * acc[mi][nj][h * 2 + c]);
                            if (d < w3[rs]) {
                                ld3[rs][2] = d; li3[rs][2] = n;
                                if (ld3[rs][2] < ld3[rs][1]) {
                                    float td = ld3[rs][2]; ld3[rs][2] = ld3[rs][1]; ld3[rs][1] = td;
                                    int ti = li3[rs][2]; li3[rs][2] = li3[rs][1]; li3[rs][1] = ti;
                                }
                                if (ld3[rs][1] < ld3[rs][0]) {
                                    float td = ld3[rs][1]; ld3[rs][1] = ld3[rs][0]; ld3[rs][0] = td;
                                    int ti = li3[rs][1]; li3[rs][1] = li3[rs][0]; li3[rs][0] = ti;
                                }
                                w3[rs] = ld3[rs][2];
                            }
                        }
                    }
                }
            }
        }
    }
    asm volatile("cp.async.wait_group 0;" ::: "memory");

#pragma unroll
    for (int rs = 0; rs < 4; rs++) {
        const int mi = rs >> 1, h = rs & 1;
        const int row = rowBlock + wm * 32 + mi * 16 + h * 8 + (l >> 2);
        const int slot = wn * 4 + (l & 3);
        const int base = row * 48 + slot * 3;
#pragma unroll
        for (int j = 0; j < 3; j++) {
            g_cd[base + j] = ld3[rs][j];
            g_ci[base + j] = li3[rs][j];
        }
    }
}

// ---------------------------------------------------------------------------
// Pass 2: exact fp32 refinement (bit-identical to R1 numerics). Warp per row.
// ---------------------------------------------------------------------------
__global__ __launch_bounds__(256) void refine_kernel(const float* __restrict__ z,
                                                     const float* __restrict__ emb) {
    const int row  = (blockIdx.x * blockDim.x + threadIdx.x) >> 5;
    const int lane = threadIdx.x & 31;
    const int base = row * 48;

    float da = g_cd[base + lane];
    int   ia = g_ci[base + lane];
    float db = (lane < 16) ? g_cd[base + 32 + lane] : FINF;
    int   ib = (lane < 16) ? g_ci[base + 32 + lane] : 0x7fffffff;

    float m = fminf(da, db);
#pragma unroll
    for (int off = 16; off > 0; off >>= 1)
        m = fminf(m, __shfl_xor_sync(0xffffffffu, m, off));
    const float thr = m + EPS_MARGIN;

    const float* zp = z + (size_t)row * DDIM;
    const float zf2 = g_zf2[row];

    float fa = FINF, fb = FINF;
    if (da <= thr) {
        const float* ep = emb + (size_t)ia * DDIM;
        float acc = 0.0f;
        for (int k = 0; k < DDIM; k++) acc = fmaf(zp[k], ep[k], acc);
        fa = __fadd_rn(__fadd_rn(zf2, g_en2[ia]), -2.0f * acc);
    } else ia = 0x7fffffff;
    if (db <= thr) {
        const float* ep = emb + (size_t)ib * DDIM;
        float acc = 0.0f;
        for (int k = 0; k < DDIM; k++) acc = fmaf(zp[k], ep[k], acc);
        fb = __fadd_rn(__fadd_rn(zf2, g_en2[ib]), -2.0f * acc);
    } else ib = 0x7fffffff;

    float bd = fa; int bi = ia;
    if (fb < bd || (fb == bd && ib < bi)) { bd = fb; bi = ib; }
#pragma unroll
    for (int off = 16; off > 0; off >>= 1) {
        float od = __shfl_xor_sync(0xffffffffu, bd, off);
        int   oi = __shfl_xor_sync(0xffffffffu, bi, off);
        if (od < bd || (od == bd && oi < bi)) { bd = od; bi = oi; }
    }
    if (lane == 0) g_idx[row] = bi;
}

// ---------------------------------------------------------------------------
__global__ void gather_loss_kernel(const float* __restrict__ z,
                                   const float* __restrict__ emb,
                                   float* __restrict__ out) {
    __shared__ double red[256];
    const int bid = blockIdx.x;            // 1024 blocks
    const int base4 = bid * 2048;          // float4 units
    double s = 0.0;
#pragma unroll 4
    for (int it = 0; it < 8; ++it) {
        const int g = base4 + it * 256 + threadIdx.x;
        const int row = g >> 7;
        const int k4  = g & 127;
        float4 v = *reinterpret_cast<const float4*>(
            emb + (size_t)g_idx[row] * DDIM + k4 * 4);
        *reinterpret_cast<float4*>(out + (size_t)g * 4) = v;
        float4 zz = *reinterpret_cast<const float4*>(z + (size_t)g * 4);
        float dx = v.x - zz.x, dy = v.y - zz.y;
        float dz = v.z - zz.z, dw = v.w - zz.w;
        s += (double)dx * dx + (double)dy * dy + (double)dz * dz + (double)dw * dw;
    }
    red[threadIdx.x] = s;
    __syncthreads();
    for (int off = 128; off > 0; off >>= 1) {
        if (threadIdx.x < off) red[threadIdx.x] += red[threadIdx.x + off];
        __syncthreads();
    }
    if (threadIdx.x == 0) g_partial[bid] = red[0];
}

__global__ void finalize_kernel(float* __restrict__ out) {
    __shared__ double rs[256], rs2[256];
    double s = 0.0, s2 = 0.0;
    for (int i = threadIdx.x; i < BT; i += 256) {
        int iv = g_idx[i];
        out[IDX_OFF + i] = (float)iv;
        double dv = (double)iv;
        s += dv; s2 += dv * dv;
    }
    rs[threadIdx.x] = s; rs2[threadIdx.x] = s2;
    __syncthreads();
    for (int off = 128; off > 0; off >>= 1) {
        if (threadIdx.x < off) {
            rs[threadIdx.x]  += rs[threadIdx.x + off];
            rs2[threadIdx.x] += rs2[threadIdx.x + off];
        }
        __syncthreads();
    }
    if (threadIdx.x == 0) {
        double ls = 0.0;
        for (int i = 0; i < 1024; i++) ls += g_partial[i];
        double mse = ls / (double)ZQ_ELEMS;
        out[LOSS_OFF] = (float)((1.0 + BETA) * mse);
        double mean = rs[0] / (double)BT;
        out[VAR_OFF] = (float)(rs2[0] / (double)BT - mean * mean);
    }
}

// ---------------------------------------------------------------------------
extern "C" void kernel_launch(void* const* d_in, const int* in_sizes, int n_in,
                              void* d_out, int out_size) {
    const float* z   = (const float*)d_in[0];
    const float* emb = (const float*)d_in[1];
    float* out = (float*)d_out;

    cudaFuncSetAttribute(vq_mma_kernel,
                         cudaFuncAttributeMaxDynamicSharedMemorySize, SMEM_DYN);

    zprep_kernel<<<ZQ_ELEMS / 4 / 256, 256>>>(z);              // launch 0
    eprep_kernel<<<NE * DDIM / 4 / 256, 256>>>(emb);           // launch 1
    norms_kernel<<<(NE + BT) / 128, 128>>>(emb, z);            // launch 2
    vq_mma_kernel<<<BT / M_TILE, 512, SMEM_DYN>>>();           // launch 3 (ncu)
    refine_kernel<<<BT * 32 / 256, 256>>>(z, emb);
    gather_loss_kernel<<<1024, 256>>>(z, emb, out);
    finalize_kernel<<<1, 256>>>(out);
}